// round 2
// baseline (speedup 1.0000x reference)
#include <cuda_runtime.h>
#include <cstdint>

// ---------------- problem constants ----------------
#define Bn 1024
#define Sn 256
#define Dn 512
#define En 16
#define On 512

// ---------------- device scratch (no allocs allowed) ----------------
__device__ float g_wt[(size_t)En * On * Dn];   // 16 MB, tf32-rounded W^T [E,O,D] (K-major)
__device__ int   g_idx[Bn];
__device__ float g_gate[Bn];

// ---------------- PTX helpers ----------------
__device__ __forceinline__ uint32_t smem_u32(const void* p) {
    uint32_t a;
    asm("{ .reg .u64 t; cvta.to.shared.u64 t, %1; cvt.u32.u64 %0, t; }" : "=r"(a) : "l"(p));
    return a;
}

__device__ __forceinline__ float to_tf32(float f) {
    uint32_t u;
    asm("cvt.rna.tf32.f32 %0, %1;" : "=r"(u) : "f"(f));
    return __uint_as_float(u);
}

__device__ __forceinline__ void cvt_tf32_inplace(uint32_t& r) {
    asm("cvt.rna.tf32.f32 %0, %0;" : "+r"(r));
}

// xor-swizzle: 16B segment index ^= (row & 7); conflict-free for ldmatrix columns
#define SWZ(o) ((o) ^ (((o) >> 3) & 0x70))

__device__ __forceinline__ void cp_async16(uint32_t dst, const void* src) {
    asm volatile("cp.async.cg.shared.global [%0], [%1], 16;" :: "r"(dst), "l"(src) : "memory");
}
#define CP_COMMIT() asm volatile("cp.async.commit_group;" ::: "memory")
#define CP_WAIT(n)  asm volatile("cp.async.wait_group %0;"  :: "n"(n) : "memory")

#define LDSM_X4(r0, r1, r2, r3, addr) \
    asm volatile("ldmatrix.sync.aligned.m8n8.x4.shared.b16 {%0,%1,%2,%3}, [%4];" \
        : "=r"(r0), "=r"(r1), "=r"(r2), "=r"(r3) : "r"(addr))

// D(16x8,f32) += A(16x8,tf32) * B(8x8,tf32)
#define MMA_TF32(d, a, b) \
    asm volatile("mma.sync.aligned.m16n8k8.row.col.f32.tf32.tf32.f32 " \
        "{%0,%1,%2,%3}, {%4,%5,%6,%7}, {%8,%9}, {%0,%1,%2,%3};" \
        : "+f"((d)[0]), "+f"((d)[1]), "+f"((d)[2]), "+f"((d)[3]) \
        : "r"((a)[0]), "r"((a)[1]), "r"((a)[2]), "r"((a)[3]), \
          "r"((b)[0]), "r"((b)[1]))

// ---------------- kernel 1: W transpose + tf32 round:  Wt[e][o][d] = rna(We[e][d][o])
__global__ void prep_w_kernel(const float* __restrict__ We) {
    __shared__ float t[32][33];
    int e = blockIdx.z, d0 = blockIdx.x * 32, o0 = blockIdx.y * 32;
    int tx = threadIdx.x, ty = threadIdx.y;
    const float* src = We + (size_t)e * Dn * On;
    float* dst = g_wt + (size_t)e * On * Dn;
    for (int r = ty; r < 32; r += 8)
        t[r][tx] = src[(size_t)(d0 + r) * On + o0 + tx];
    __syncthreads();
    for (int r = ty; r < 32; r += 8)
        dst[(size_t)(o0 + r) * Dn + d0 + tx] = to_tf32(t[tx][r]);
}

// ---------------- kernel 2: routing (Kahan mean -> fp64 linear -> softmax/argmax)
__global__ __launch_bounds__(256) void routing_kernel(
    const float* __restrict__ x, const float* __restrict__ Wg, const float* __restrict__ bg)
{
    __shared__ float smean[Dn];
    __shared__ float sscore[En];
    int b = blockIdx.x, tid = threadIdx.x;
    int wid = tid >> 5, lane = tid & 31;

    const float* xb = x + (size_t)b * Sn * Dn;

    // Kahan-compensated fp32 sums over S for 2 columns per thread
    float s0 = 0.f, c0 = 0.f, s1 = 0.f, c1 = 0.f;
    for (int s = 0; s < Sn; s++) {
        float f0 = xb[s * Dn + tid];
        float f1 = xb[s * Dn + tid + 256];
        float y0 = f0 - c0; float t0 = s0 + y0; c0 = (t0 - s0) - y0; s0 = t0;
        float y1 = f1 - c1; float t1 = s1 + y1; c1 = (t1 - s1) - y1; s1 = t1;
    }
    smean[tid]       = s0 * (1.0f / Sn);
    smean[tid + 256] = s1 * (1.0f / Sn);
    __syncthreads();

    // 8 warps x 2 experts: fp64 dot over D=512 (tiny: 16*512 DFMA per CTA)
    for (int e = wid; e < En; e += 8) {
        double p = 0.0;
        for (int d = lane; d < Dn; d += 32)
            p += (double)smean[d] * (double)Wg[d * En + e];
        #pragma unroll
        for (int o = 16; o > 0; o >>= 1)
            p += __shfl_down_sync(0xFFFFFFFFu, p, o);
        if (lane == 0) sscore[e] = (float)(p + (double)bg[e]);
    }
    __syncthreads();

    if (tid == 0) {
        float m = sscore[0];
        int bi = 0;
        #pragma unroll
        for (int e = 1; e < En; e++)
            if (sscore[e] > m) { m = sscore[e]; bi = e; }   // first-max == jnp.argmax
        float den = 0.0f;
        #pragma unroll
        for (int e = 0; e < En; e++) den += expf(sscore[e] - m);
        g_idx[b]  = bi;
        g_gate[b] = 1.0f / den;   // top-1 softmax prob
    }
}

// ---------------- kernel 3: per-batch GEMM, mma.sync tf32 ----------------
// CTA tile M=128 x N=128, K in 16 chunks of 32. 8 warps: 4(M) x 2(N), warp tile 32x64.
#define STAGES 4
#define KC 32
#define A_ST (128 * KC * 4)                 // 16 KB
#define B_ST (128 * KC * 4)                 // 16 KB
#define STAGE_BYTES (A_ST + B_ST)           // 32 KB
#define GEMM_SMEM (STAGES * STAGE_BYTES)    // 128 KB
#define NCHUNK (Dn / KC)                    // 16

__global__ __launch_bounds__(256, 1) void moe_gemm_kernel(
    const float* __restrict__ x, const float* __restrict__ be, float* __restrict__ out)
{
    extern __shared__ char smem[];
    const uint32_t sb = smem_u32(smem);
    const int tid  = threadIdx.x;
    const int wid  = tid >> 5;
    const int lane = tid & 31;

    const int bx = blockIdx.x;
    const int b  = bx >> 3;          // batch
    const int mt = (bx >> 2) & 1;    // M tile (2 x 128)
    const int nt = bx & 3;           // N tile (4 x 128)

    const int   e    = g_idx[b];
    const float gate = g_gate[b];

    const char* agbase = (const char*)(x    + ((size_t)b * Sn + mt * 128) * Dn);
    const char* bgbase = (const char*)(g_wt + ((size_t)e * On + nt * 128) * Dn);

    const int warp_m = wid & 3;      // 0..3 -> 32-row slabs
    const int warp_n = wid >> 2;     // 0..1 -> 64-col slabs

    auto load_stage = [&](int c) {
        const int st = c & (STAGES - 1);
        const uint32_t abase = sb + st * STAGE_BYTES;
        const uint32_t bbase = abase + A_ST;
        #pragma unroll
        for (int j = 0; j < 4; j++) {               // A: 1024 x 16B over 256 thr
            int idx = j * 256 + tid;
            int row = idx >> 3, seg = idx & 7;
            uint32_t off = row * 128 + seg * 16;
            cp_async16(abase + SWZ(off), agbase + (size_t)row * (Dn * 4) + c * (KC * 4) + seg * 16);
        }
        #pragma unroll
        for (int j = 0; j < 4; j++) {               // B: 1024 x 16B
            int idx = j * 256 + tid;
            int row = idx >> 3, seg = idx & 7;
            uint32_t off = row * 128 + seg * 16;
            cp_async16(bbase + SWZ(off), bgbase + (size_t)row * (Dn * 4) + c * (KC * 4) + seg * 16);
        }
        CP_COMMIT();
    };

    float acc[2][8][4];
    #pragma unroll
    for (int i = 0; i < 2; i++)
        #pragma unroll
        for (int j = 0; j < 8; j++)
            #pragma unroll
            for (int k = 0; k < 4; k++) acc[i][j][k] = 0.f;

    load_stage(0);
    load_stage(1);
    load_stage(2);

    // ldmatrix lane->address precomputation
    // A: row = m_base + (lane&15), k-half = lane>>4
    // B: row = n_base + ((lane>>4)<<3) + (lane&7), k-half = (lane>>3)&1
    const int a_row  = warp_m * 32 + (lane & 15);
    const int a_kh   = (lane >> 4);
    const int b_row0 = warp_n * 64 + ((lane >> 4) << 3) + (lane & 7);
    const int b_kh   = (lane >> 3) & 1;

    for (int c = 0; c < NCHUNK; c++) {
        if (c <= NCHUNK - 3) { CP_WAIT(2); }
        else if (c == NCHUNK - 2) { CP_WAIT(1); }
        else { CP_WAIT(0); }
        __syncthreads();

        if (c + 3 < NCHUNK) load_stage(c + 3);

        const uint32_t abase = sb + (c & (STAGES - 1)) * STAGE_BYTES;
        const uint32_t bbase = abase + A_ST;

        #pragma unroll
        for (int ks = 0; ks < 4; ks++) {
            uint32_t a[2][4];
            #pragma unroll
            for (int mf = 0; mf < 2; mf++) {
                uint32_t off = (a_row + mf * 16) * 128 + ks * 32 + a_kh * 16;
                LDSM_X4(a[mf][0], a[mf][1], a[mf][2], a[mf][3], abase + SWZ(off));
            }
            // round A to tf32 (RNA) in-register: avoids truncation bias
            #pragma unroll
            for (int mf = 0; mf < 2; mf++)
                #pragma unroll
                for (int i = 0; i < 4; i++) cvt_tf32_inplace(a[mf][i]);

            uint32_t bf[8][2];
            #pragma unroll
            for (int np = 0; np < 4; np++) {
                uint32_t off = (b_row0 + np * 16) * 128 + ks * 32 + b_kh * 16;
                LDSM_X4(bf[np * 2][0], bf[np * 2][1], bf[np * 2 + 1][0], bf[np * 2 + 1][1],
                        bbase + SWZ(off));
            }

            #pragma unroll
            for (int mf = 0; mf < 2; mf++)
                #pragma unroll
                for (int nf = 0; nf < 8; nf++)
                    MMA_TF32(acc[mf][nf], a[mf], bf[nf]);
        }
    }

    // epilogue: gate * (acc + bias)
    const int g = lane >> 2, t = lane & 3;
    const float* bias = be + (size_t)e * On + nt * 128 + warp_n * 64;
    float* obase = out + ((size_t)b * Sn + mt * 128 + warp_m * 32 + g) * On
                       + nt * 128 + warp_n * 64;
    #pragma unroll
    for (int mf = 0; mf < 2; mf++) {
        #pragma unroll
        for (int nf = 0; nf < 8; nf++) {
            int col = nf * 8 + t * 2;
            float b0 = __ldg(bias + col);
            float b1 = __ldg(bias + col + 1);
            float2 v0, v1;
            v0.x = gate * (acc[mf][nf][0] + b0);
            v0.y = gate * (acc[mf][nf][1] + b1);
            v1.x = gate * (acc[mf][nf][2] + b0);
            v1.y = gate * (acc[mf][nf][3] + b1);
            *(float2*)(obase + (size_t)(mf * 16) * On + col)     = v0;
            *(float2*)(obase + (size_t)(mf * 16 + 8) * On + col) = v1;
        }
    }
}

// ---------------- entry point ----------------
extern "C" void kernel_launch(void* const* d_in, const int* in_sizes, int n_in,
                              void* d_out, int out_size)
{
    const float* x  = (const float*)d_in[0];
    const float* Wg = (const float*)d_in[1];
    const float* bg = (const float*)d_in[2];
    const float* We = (const float*)d_in[3];
    const float* be = (const float*)d_in[4];
    float* out = (float*)d_out;

    cudaFuncSetAttribute(moe_gemm_kernel,
                         cudaFuncAttributeMaxDynamicSharedMemorySize, GEMM_SMEM);

    prep_w_kernel<<<dim3(Dn / 32, On / 32, En), dim3(32, 8)>>>(We);
    routing_kernel<<<Bn, 256>>>(x, Wg, bg);
    moe_gemm_kernel<<<Bn * 8, 256, GEMM_SMEM>>>(x, be, out);
}

// round 3
// speedup vs baseline: 1.1241x; 1.1241x over previous
#include <cuda_runtime.h>
#include <cstdint>

// ---------------- problem constants ----------------
#define Bn 1024
#define Sn 256
#define Dn 512
#define En 16
#define On 512

// ---------------- device scratch (no allocs allowed) ----------------
__device__ float g_x[(size_t)Bn * Sn * Dn];    // 512 MB, tf32-rounded x
__device__ float g_wt[(size_t)En * On * Dn];   // 16 MB, tf32-rounded W^T [E,O,D] (K-major)
__device__ int   g_idx[Bn];
__device__ float g_gate[Bn];

// ---------------- PTX helpers ----------------
__device__ __forceinline__ uint32_t smem_u32(const void* p) {
    uint32_t a;
    asm("{ .reg .u64 t; cvta.to.shared.u64 t, %1; cvt.u32.u64 %0, t; }" : "=r"(a) : "l"(p));
    return a;
}

__device__ __forceinline__ float to_tf32(float f) {
    uint32_t u;
    asm("cvt.rna.tf32.f32 %0, %1;" : "=r"(u) : "f"(f));
    return __uint_as_float(u);
}

// xor-swizzle: 16B segment index ^= (row & 7); conflict-free for ldmatrix columns
#define SWZ(o) ((o) ^ (((o) >> 3) & 0x70))

__device__ __forceinline__ void cp_async16(uint32_t dst, const void* src) {
    asm volatile("cp.async.cg.shared.global [%0], [%1], 16;" :: "r"(dst), "l"(src) : "memory");
}
#define CP_COMMIT() asm volatile("cp.async.commit_group;" ::: "memory")
#define CP_WAIT(n)  asm volatile("cp.async.wait_group %0;"  :: "n"(n) : "memory")

#define LDSM_X4(r0, r1, r2, r3, addr) \
    asm volatile("ldmatrix.sync.aligned.m8n8.x4.shared.b16 {%0,%1,%2,%3}, [%4];" \
        : "=r"(r0), "=r"(r1), "=r"(r2), "=r"(r3) : "r"(addr))

// D(16x8,f32) += A(16x8,tf32) * B(8x8,tf32)
#define MMA_TF32(d, a, b) \
    asm volatile("mma.sync.aligned.m16n8k8.row.col.f32.tf32.tf32.f32 " \
        "{%0,%1,%2,%3}, {%4,%5,%6,%7}, {%8,%9}, {%0,%1,%2,%3};" \
        : "+f"((d)[0]), "+f"((d)[1]), "+f"((d)[2]), "+f"((d)[3]) \
        : "r"((a)[0]), "r"((a)[1]), "r"((a)[2]), "r"((a)[3]), \
          "r"((b)[0]), "r"((b)[1]))

// ---------------- kernel 1: W transpose + tf32 round:  Wt[e][o][d] = rna(We[e][d][o])
__global__ void prep_w_kernel(const float* __restrict__ We) {
    __shared__ float t[32][33];
    int e = blockIdx.z, d0 = blockIdx.x * 32, o0 = blockIdx.y * 32;
    int tx = threadIdx.x, ty = threadIdx.y;
    const float* src = We + (size_t)e * Dn * On;
    float* dst = g_wt + (size_t)e * On * Dn;
    for (int r = ty; r < 32; r += 8)
        t[r][tx] = src[(size_t)(d0 + r) * On + o0 + tx];
    __syncthreads();
    for (int r = ty; r < 32; r += 8)
        dst[(size_t)(o0 + r) * Dn + d0 + tx] = to_tf32(t[tx][r]);
}

// ---------------- kernel 2: routing + x tf32 conversion (fused single pass over x)
__global__ __launch_bounds__(256) void routing_kernel(
    const float* __restrict__ x, const float* __restrict__ Wg, const float* __restrict__ bg)
{
    __shared__ float smean[Dn];
    __shared__ float sscore[En];
    int b = blockIdx.x, tid = threadIdx.x;
    int wid = tid >> 5, lane = tid & 31;

    const float* xb = x   + (size_t)b * Sn * Dn;
    float*       xc = g_x + (size_t)b * Sn * Dn;

    // Kahan-compensated fp32 sums over S for 2 columns per thread; write tf32 copy
    float s0 = 0.f, c0 = 0.f, s1 = 0.f, c1 = 0.f;
    for (int s = 0; s < Sn; s++) {
        float f0 = xb[s * Dn + tid];
        float f1 = xb[s * Dn + tid + 256];
        xc[s * Dn + tid]       = to_tf32(f0);
        xc[s * Dn + tid + 256] = to_tf32(f1);
        float y0 = f0 - c0; float t0 = s0 + y0; c0 = (t0 - s0) - y0; s0 = t0;
        float y1 = f1 - c1; float t1 = s1 + y1; c1 = (t1 - s1) - y1; s1 = t1;
    }
    smean[tid]       = s0 * (1.0f / Sn);
    smean[tid + 256] = s1 * (1.0f / Sn);
    __syncthreads();

    // 8 warps x 2 experts: fp64 dot over D=512 (tiny)
    for (int e = wid; e < En; e += 8) {
        double p = 0.0;
        for (int d = lane; d < Dn; d += 32)
            p += (double)smean[d] * (double)Wg[d * En + e];
        #pragma unroll
        for (int o = 16; o > 0; o >>= 1)
            p += __shfl_down_sync(0xFFFFFFFFu, p, o);
        if (lane == 0) sscore[e] = (float)(p + (double)bg[e]);
    }
    __syncthreads();

    if (tid == 0) {
        float m = sscore[0];
        int bi = 0;
        #pragma unroll
        for (int e = 1; e < En; e++)
            if (sscore[e] > m) { m = sscore[e]; bi = e; }   // first-max == jnp.argmax
        float den = 0.0f;
        #pragma unroll
        for (int e = 0; e < En; e++) den += expf(sscore[e] - m);
        g_idx[b]  = bi;
        g_gate[b] = 1.0f / den;   // top-1 softmax prob
    }
}

// ---------------- kernel 3: per-batch GEMM, mma.sync tf32 ----------------
// CTA tile M=128 x N=128, K in 16 chunks of 32. 8 warps: 4(M) x 2(N), warp tile 32x64.
// 3 stages x 32KB = 96KB smem -> 2 CTAs/SM.
#define STAGES 3
#define KC 32
#define A_ST (128 * KC * 4)                 // 16 KB
#define B_ST (128 * KC * 4)                 // 16 KB
#define STAGE_BYTES (A_ST + B_ST)           // 32 KB
#define GEMM_SMEM (STAGES * STAGE_BYTES)    // 96 KB
#define NCHUNK (Dn / KC)                    // 16

__global__ __launch_bounds__(256, 2) void moe_gemm_kernel(
    const float* __restrict__ be, float* __restrict__ out)
{
    extern __shared__ char smem[];
    const uint32_t sb = smem_u32(smem);
    const int tid  = threadIdx.x;
    const int wid  = tid >> 5;
    const int lane = tid & 31;

    const int bx = blockIdx.x;
    const int b  = bx >> 3;          // batch
    const int mt = (bx >> 2) & 1;    // M tile (2 x 128)
    const int nt = bx & 3;           // N tile (4 x 128)

    const int   e    = g_idx[b];
    const float gate = g_gate[b];

    const char* agbase = (const char*)(g_x  + ((size_t)b * Sn + mt * 128) * Dn);
    const char* bgbase = (const char*)(g_wt + ((size_t)e * On + nt * 128) * Dn);

    const int warp_m = wid & 3;      // 0..3 -> 32-row slabs
    const int warp_n = wid >> 2;     // 0..1 -> 64-col slabs

    auto load_stage = [&](int c) {
        const int st = c % STAGES;
        const uint32_t abase = sb + st * STAGE_BYTES;
        const uint32_t bbase = abase + A_ST;
        #pragma unroll
        for (int j = 0; j < 4; j++) {               // A: 1024 x 16B over 256 thr
            int idx = j * 256 + tid;
            int row = idx >> 3, seg = idx & 7;
            uint32_t off = row * 128 + seg * 16;
            cp_async16(abase + SWZ(off), agbase + (size_t)row * (Dn * 4) + c * (KC * 4) + seg * 16);
        }
        #pragma unroll
        for (int j = 0; j < 4; j++) {               // B: 1024 x 16B
            int idx = j * 256 + tid;
            int row = idx >> 3, seg = idx & 7;
            uint32_t off = row * 128 + seg * 16;
            cp_async16(bbase + SWZ(off), bgbase + (size_t)row * (Dn * 4) + c * (KC * 4) + seg * 16);
        }
        CP_COMMIT();
    };

    float acc[2][8][4];
    #pragma unroll
    for (int i = 0; i < 2; i++)
        #pragma unroll
        for (int j = 0; j < 8; j++)
            #pragma unroll
            for (int k = 0; k < 4; k++) acc[i][j][k] = 0.f;

    load_stage(0);
    load_stage(1);

    // ldmatrix lane->address precomputation
    const int a_row  = warp_m * 32 + (lane & 15);
    const int a_kh   = (lane >> 4);
    const int b_row0 = warp_n * 64 + ((lane >> 4) << 3) + (lane & 7);
    const int b_kh   = (lane >> 3) & 1;

    for (int c = 0; c < NCHUNK; c++) {
        if (c < NCHUNK - 1) { CP_WAIT(1); } else { CP_WAIT(0); }
        __syncthreads();

        if (c + 2 < NCHUNK) load_stage(c + 2);

        const uint32_t abase = sb + (c % STAGES) * STAGE_BYTES;
        const uint32_t bbase = abase + A_ST;

        #pragma unroll
        for (int ks = 0; ks < 4; ks++) {
            uint32_t a[2][4];
            #pragma unroll
            for (int mf = 0; mf < 2; mf++) {
                uint32_t off = (a_row + mf * 16) * 128 + ks * 32 + a_kh * 16;
                LDSM_X4(a[mf][0], a[mf][1], a[mf][2], a[mf][3], abase + SWZ(off));
            }

            uint32_t bf[8][2];
            #pragma unroll
            for (int np = 0; np < 4; np++) {
                uint32_t off = (b_row0 + np * 16) * 128 + ks * 32 + b_kh * 16;
                LDSM_X4(bf[np * 2][0], bf[np * 2][1], bf[np * 2 + 1][0], bf[np * 2 + 1][1],
                        bbase + SWZ(off));
            }

            #pragma unroll
            for (int mf = 0; mf < 2; mf++)
                #pragma unroll
                for (int nf = 0; nf < 8; nf++)
                    MMA_TF32(acc[mf][nf], a[mf], bf[nf]);
        }
        __syncthreads();
    }

    // epilogue: gate * (acc + bias)
    const int g = lane >> 2, t = lane & 3;
    const float* bias = be + (size_t)e * On + nt * 128 + warp_n * 64;
    float* obase = out + ((size_t)b * Sn + mt * 128 + warp_m * 32 + g) * On
                       + nt * 128 + warp_n * 64;
    #pragma unroll
    for (int mf = 0; mf < 2; mf++) {
        #pragma unroll
        for (int nf = 0; nf < 8; nf++) {
            int col = nf * 8 + t * 2;
            float b0 = __ldg(bias + col);
            float b1 = __ldg(bias + col + 1);
            float2 v0, v1;
            v0.x = gate * (acc[mf][nf][0] + b0);
            v0.y = gate * (acc[mf][nf][1] + b1);
            v1.x = gate * (acc[mf][nf][2] + b0);
            v1.y = gate * (acc[mf][nf][3] + b1);
            *(float2*)(obase + (size_t)(mf * 16) * On + col)     = v0;
            *(float2*)(obase + (size_t)(mf * 16 + 8) * On + col) = v1;
        }
    }
}

// ---------------- entry point ----------------
extern "C" void kernel_launch(void* const* d_in, const int* in_sizes, int n_in,
                              void* d_out, int out_size)
{
    const float* x  = (const float*)d_in[0];
    const float* Wg = (const float*)d_in[1];
    const float* bg = (const float*)d_in[2];
    const float* We = (const float*)d_in[3];
    const float* be = (const float*)d_in[4];
    float* out = (float*)d_out;

    cudaFuncSetAttribute(moe_gemm_kernel,
                         cudaFuncAttributeMaxDynamicSharedMemorySize, GEMM_SMEM);

    prep_w_kernel<<<dim3(Dn / 32, On / 32, En), dim3(32, 8)>>>(We);
    routing_kernel<<<Bn, 256>>>(x, Wg, bg);
    moe_gemm_kernel<<<Bn * 8, 256, GEMM_SMEM>>>(be, out);
}

// round 4
// speedup vs baseline: 1.1932x; 1.0615x over previous
#include <cuda_runtime.h>
#include <cstdint>

// ---------------- problem constants ----------------
#define Bn 1024
#define Sn 256
#define Dn 512
#define En 16
#define On 512

// ---------------- device scratch (no allocs allowed) ----------------
__device__ float g_wt[(size_t)En * On * Dn];   // 16 MB, tf32-rounded W^T [E,O,D] (K-major)
__device__ int   g_idx[Bn];
__device__ float g_gate[Bn];

// ---------------- PTX helpers ----------------
__device__ __forceinline__ uint32_t smem_u32(const void* p) {
    uint32_t a;
    asm("{ .reg .u64 t; cvta.to.shared.u64 t, %1; cvt.u32.u64 %0, t; }" : "=r"(a) : "l"(p));
    return a;
}

__device__ __forceinline__ float to_tf32(float f) {
    uint32_t u;
    asm("cvt.rna.tf32.f32 %0, %1;" : "=r"(u) : "f"(f));
    return __uint_as_float(u);
}

__device__ __forceinline__ void cvt_tf32_inplace(uint32_t& r) {
    asm("cvt.rna.tf32.f32 %0, %0;" : "+r"(r));
}

// xor-swizzle: 16B segment index ^= (row & 7); conflict-free for ldmatrix columns
#define SWZ(o) ((o) ^ (((o) >> 3) & 0x70))

__device__ __forceinline__ void cp_async16(uint32_t dst, const void* src) {
    asm volatile("cp.async.cg.shared.global [%0], [%1], 16;" :: "r"(dst), "l"(src) : "memory");
}
#define CP_COMMIT() asm volatile("cp.async.commit_group;" ::: "memory")
#define CP_WAIT(n)  asm volatile("cp.async.wait_group %0;"  :: "n"(n) : "memory")

#define LDSM_X4(r0, r1, r2, r3, addr) \
    asm volatile("ldmatrix.sync.aligned.m8n8.x4.shared.b16 {%0,%1,%2,%3}, [%4];" \
        : "=r"(r0), "=r"(r1), "=r"(r2), "=r"(r3) : "r"(addr))

// D(16x8,f32) += A(16x8,tf32) * B(8x8,tf32)
#define MMA_TF32(d, a, b) \
    asm volatile("mma.sync.aligned.m16n8k8.row.col.f32.tf32.tf32.f32 " \
        "{%0,%1,%2,%3}, {%4,%5,%6,%7}, {%8,%9}, {%0,%1,%2,%3};" \
        : "+f"((d)[0]), "+f"((d)[1]), "+f"((d)[2]), "+f"((d)[3]) \
        : "r"((a)[0]), "r"((a)[1]), "r"((a)[2]), "r"((a)[3]), \
          "r"((b)[0]), "r"((b)[1]))

// ---------------- kernel 1: W transpose + tf32 round:  Wt[e][o][d] = rna(We[e][d][o])
__global__ void prep_w_kernel(const float* __restrict__ We) {
    __shared__ float t[32][33];
    int e = blockIdx.z, d0 = blockIdx.x * 32, o0 = blockIdx.y * 32;
    int tx = threadIdx.x, ty = threadIdx.y;
    const float* src = We + (size_t)e * Dn * On;
    float* dst = g_wt + (size_t)e * On * Dn;
    for (int r = ty; r < 32; r += 8)
        t[r][tx] = src[(size_t)(d0 + r) * On + o0 + tx];
    __syncthreads();
    for (int r = ty; r < 32; r += 8)
        dst[(size_t)(o0 + r) * Dn + d0 + tx] = to_tf32(t[tx][r]);
}

// ---------------- kernel 2: routing (Kahan mean -> fp64 linear -> softmax/argmax)
__global__ __launch_bounds__(256) void routing_kernel(
    const float* __restrict__ x, const float* __restrict__ Wg, const float* __restrict__ bg)
{
    __shared__ float smean[Dn];
    __shared__ float sscore[En];
    int b = blockIdx.x, tid = threadIdx.x;
    int wid = tid >> 5, lane = tid & 31;

    const float2* xb = (const float2*)(x + (size_t)b * Sn * Dn);

    // Kahan-compensated fp32 sums over S; thread t owns columns 2t, 2t+1
    float s0 = 0.f, c0 = 0.f, s1 = 0.f, c1 = 0.f;
    #pragma unroll 4
    for (int s = 0; s < Sn; s++) {
        float2 f = xb[s * (Dn / 2) + tid];
        float y0 = f.x - c0; float t0 = s0 + y0; c0 = (t0 - s0) - y0; s0 = t0;
        float y1 = f.y - c1; float t1 = s1 + y1; c1 = (t1 - s1) - y1; s1 = t1;
    }
    smean[2 * tid]     = s0 * (1.0f / Sn);
    smean[2 * tid + 1] = s1 * (1.0f / Sn);
    __syncthreads();

    // 8 warps x 2 experts: fp64 dot over D=512 (tiny)
    for (int e = wid; e < En; e += 8) {
        double p = 0.0;
        for (int d = lane; d < Dn; d += 32)
            p += (double)smean[d] * (double)Wg[d * En + e];
        #pragma unroll
        for (int o = 16; o > 0; o >>= 1)
            p += __shfl_down_sync(0xFFFFFFFFu, p, o);
        if (lane == 0) sscore[e] = (float)(p + (double)bg[e]);
    }
    __syncthreads();

    if (tid == 0) {
        float m = sscore[0];
        int bi = 0;
        #pragma unroll
        for (int e = 1; e < En; e++)
            if (sscore[e] > m) { m = sscore[e]; bi = e; }   // first-max == jnp.argmax
        float den = 0.0f;
        #pragma unroll
        for (int e = 0; e < En; e++) den += expf(sscore[e] - m);
        g_idx[b]  = bi;
        g_gate[b] = 1.0f / den;   // top-1 softmax prob
    }
}

// ---------------- kernel 3: per-batch GEMM, mma.sync tf32 ----------------
// CTA tile M=128 x N=128, K in 16 chunks of 32. 8 warps: 4(M) x 2(N), warp tile 32x64.
// 3 stages x 32KB = 96KB smem -> 2 CTAs/SM. A read raw from x, RNA->tf32 in registers.
#define STAGES 3
#define KC 32
#define A_ST (128 * KC * 4)                 // 16 KB
#define B_ST (128 * KC * 4)                 // 16 KB
#define STAGE_BYTES (A_ST + B_ST)           // 32 KB
#define GEMM_SMEM (STAGES * STAGE_BYTES)    // 96 KB
#define NCHUNK (Dn / KC)                    // 16

__global__ __launch_bounds__(256, 2) void moe_gemm_kernel(
    const float* __restrict__ x, const float* __restrict__ be, float* __restrict__ out)
{
    extern __shared__ char smem[];
    const uint32_t sb = smem_u32(smem);
    const int tid  = threadIdx.x;
    const int wid  = tid >> 5;
    const int lane = tid & 31;

    const int bx = blockIdx.x;
    const int b  = bx >> 3;          // batch
    const int mt = (bx >> 2) & 1;    // M tile (2 x 128)
    const int nt = bx & 3;           // N tile (4 x 128)

    const int   e    = g_idx[b];
    const float gate = g_gate[b];

    const char* agbase = (const char*)(x    + ((size_t)b * Sn + mt * 128) * Dn);
    const char* bgbase = (const char*)(g_wt + ((size_t)e * On + nt * 128) * Dn);

    const int warp_m = wid & 3;      // 0..3 -> 32-row slabs
    const int warp_n = wid >> 2;     // 0..1 -> 64-col slabs

    auto load_stage = [&](int c) {
        const int st = c % STAGES;
        const uint32_t abase = sb + st * STAGE_BYTES;
        const uint32_t bbase = abase + A_ST;
        #pragma unroll
        for (int j = 0; j < 4; j++) {               // A: 1024 x 16B over 256 thr
            int idx = j * 256 + tid;
            int row = idx >> 3, seg = idx & 7;
            uint32_t off = row * 128 + seg * 16;
            cp_async16(abase + SWZ(off), agbase + (size_t)row * (Dn * 4) + c * (KC * 4) + seg * 16);
        }
        #pragma unroll
        for (int j = 0; j < 4; j++) {               // B: 1024 x 16B
            int idx = j * 256 + tid;
            int row = idx >> 3, seg = idx & 7;
            uint32_t off = row * 128 + seg * 16;
            cp_async16(bbase + SWZ(off), bgbase + (size_t)row * (Dn * 4) + c * (KC * 4) + seg * 16);
        }
        CP_COMMIT();
    };

    float acc[2][8][4];
    #pragma unroll
    for (int i = 0; i < 2; i++)
        #pragma unroll
        for (int j = 0; j < 8; j++)
            #pragma unroll
            for (int k = 0; k < 4; k++) acc[i][j][k] = 0.f;

    load_stage(0);
    load_stage(1);

    // ldmatrix lane->address precomputation
    const int a_row  = warp_m * 32 + (lane & 15);
    const int a_kh   = (lane >> 4);
    const int b_row0 = warp_n * 64 + ((lane >> 4) << 3) + (lane & 7);
    const int b_kh   = (lane >> 3) & 1;

    for (int c = 0; c < NCHUNK; c++) {
        if (c < NCHUNK - 1) { CP_WAIT(1); } else { CP_WAIT(0); }
        __syncthreads();
        // Single barrier per chunk: all warps finished compute(c-1) before any
        // passes this barrier, so overwriting stage (c+2)%3 == (c-1)%3 is safe.
        if (c + 2 < NCHUNK) load_stage(c + 2);

        const uint32_t abase = sb + (c % STAGES) * STAGE_BYTES;
        const uint32_t bbase = abase + A_ST;

        #pragma unroll
        for (int ks = 0; ks < 4; ks++) {
            uint32_t a[2][4];
            #pragma unroll
            for (int mf = 0; mf < 2; mf++) {
                uint32_t off = (a_row + mf * 16) * 128 + ks * 32 + a_kh * 16;
                LDSM_X4(a[mf][0], a[mf][1], a[mf][2], a[mf][3], abase + SWZ(off));
            }
            // RNA-round A to tf32 in registers (raw fp32 would truncate -> bias)
            #pragma unroll
            for (int mf = 0; mf < 2; mf++)
                #pragma unroll
                for (int i = 0; i < 4; i++) cvt_tf32_inplace(a[mf][i]);

            uint32_t bf[8][2];
            #pragma unroll
            for (int np = 0; np < 4; np++) {
                uint32_t off = (b_row0 + np * 16) * 128 + ks * 32 + b_kh * 16;
                LDSM_X4(bf[np * 2][0], bf[np * 2][1], bf[np * 2 + 1][0], bf[np * 2 + 1][1],
                        bbase + SWZ(off));
            }

            #pragma unroll
            for (int mf = 0; mf < 2; mf++)
                #pragma unroll
                for (int nf = 0; nf < 8; nf++)
                    MMA_TF32(acc[mf][nf], a[mf], bf[nf]);
        }
    }

    // epilogue: gate * (acc + bias)
    const int g = lane >> 2, t = lane & 3;
    const float* bias = be + (size_t)e * On + nt * 128 + warp_n * 64;
    float* obase = out + ((size_t)b * Sn + mt * 128 + warp_m * 32 + g) * On
                       + nt * 128 + warp_n * 64;
    #pragma unroll
    for (int mf = 0; mf < 2; mf++) {
        #pragma unroll
        for (int nf = 0; nf < 8; nf++) {
            int col = nf * 8 + t * 2;
            float b0 = __ldg(bias + col);
            float b1 = __ldg(bias + col + 1);
            float2 v0, v1;
            v0.x = gate * (acc[mf][nf][0] + b0);
            v0.y = gate * (acc[mf][nf][1] + b1);
            v1.x = gate * (acc[mf][nf][2] + b0);
            v1.y = gate * (acc[mf][nf][3] + b1);
            *(float2*)(obase + (size_t)(mf * 16) * On + col)     = v0;
            *(float2*)(obase + (size_t)(mf * 16 + 8) * On + col) = v1;
        }
    }
}

// ---------------- entry point ----------------
extern "C" void kernel_launch(void* const* d_in, const int* in_sizes, int n_in,
                              void* d_out, int out_size)
{
    const float* x  = (const float*)d_in[0];
    const float* Wg = (const float*)d_in[1];
    const float* bg = (const float*)d_in[2];
    const float* We = (const float*)d_in[3];
    const float* be = (const float*)d_in[4];
    float* out = (float*)d_out;

    cudaFuncSetAttribute(moe_gemm_kernel,
                         cudaFuncAttributeMaxDynamicSharedMemorySize, GEMM_SMEM);

    // Order chosen so ncu (-s 5 -c 1) captures moe_gemm_kernel next profile.
    routing_kernel<<<Bn, 256>>>(x, Wg, bg);
    prep_w_kernel<<<dim3(Dn / 32, On / 32, En), dim3(32, 8)>>>(We);
    moe_gemm_kernel<<<Bn * 8, 256, GEMM_SMEM>>>(x, be, out);
}

// round 5
// speedup vs baseline: 1.2088x; 1.0130x over previous
#include <cuda_runtime.h>
#include <cstdint>

// ---------------- problem constants ----------------
#define Bn 1024
#define Sn 256
#define Dn 512
#define En 16
#define On 512

// ---------------- device scratch (no allocs allowed) ----------------
__device__ float g_wt[(size_t)En * On * Dn];   // 16 MB, tf32-rounded W^T [E,O,D] (K-major)
__device__ int   g_idx[Bn];
__device__ float g_gate[Bn];

// ---------------- PTX helpers ----------------
__device__ __forceinline__ uint32_t smem_u32(const void* p) {
    uint32_t a;
    asm("{ .reg .u64 t; cvta.to.shared.u64 t, %1; cvt.u32.u64 %0, t; }" : "=r"(a) : "l"(p));
    return a;
}

__device__ __forceinline__ float to_tf32(float f) {
    uint32_t u;
    asm("cvt.rna.tf32.f32 %0, %1;" : "=r"(u) : "f"(f));
    return __uint_as_float(u);
}

__device__ __forceinline__ void cvt_tf32_inplace(uint32_t& r) {
    asm("cvt.rna.tf32.f32 %0, %0;" : "+r"(r));
}

// xor-swizzle: 16B segment index ^= (row & 7); conflict-free for ldmatrix columns
#define SWZ(o) ((o) ^ (((o) >> 3) & 0x70))

__device__ __forceinline__ void cp_async16(uint32_t dst, const void* src) {
    asm volatile("cp.async.cg.shared.global [%0], [%1], 16;" :: "r"(dst), "l"(src) : "memory");
}
#define CP_COMMIT() asm volatile("cp.async.commit_group;" ::: "memory")
#define CP_WAIT(n)  asm volatile("cp.async.wait_group %0;"  :: "n"(n) : "memory")

#define LDSM_X4(r0, r1, r2, r3, addr) \
    asm volatile("ldmatrix.sync.aligned.m8n8.x4.shared.b16 {%0,%1,%2,%3}, [%4];" \
        : "=r"(r0), "=r"(r1), "=r"(r2), "=r"(r3) : "r"(addr))

// D(16x8,f32) += A(16x8,tf32) * B(8x8,tf32)
#define MMA_TF32(d, a, b) \
    asm volatile("mma.sync.aligned.m16n8k8.row.col.f32.tf32.tf32.f32 " \
        "{%0,%1,%2,%3}, {%4,%5,%6,%7}, {%8,%9}, {%0,%1,%2,%3};" \
        : "+f"((d)[0]), "+f"((d)[1]), "+f"((d)[2]), "+f"((d)[3]) \
        : "r"((a)[0]), "r"((a)[1]), "r"((a)[2]), "r"((a)[3]), \
          "r"((b)[0]), "r"((b)[1]))

// ---------------- kernel 1: W transpose + tf32 round:  Wt[e][o][d] = rna(We[e][d][o])
__global__ void prep_w_kernel(const float* __restrict__ We) {
    __shared__ float t[32][33];
    int e = blockIdx.z, d0 = blockIdx.x * 32, o0 = blockIdx.y * 32;
    int tx = threadIdx.x, ty = threadIdx.y;
    const float* src = We + (size_t)e * Dn * On;
    float* dst = g_wt + (size_t)e * On * Dn;
    for (int r = ty; r < 32; r += 8)
        t[r][tx] = src[(size_t)(d0 + r) * On + o0 + tx];
    __syncthreads();
    for (int r = ty; r < 32; r += 8)
        dst[(size_t)(o0 + r) * Dn + d0 + tx] = to_tf32(t[tx][r]);
}

// ---------------- kernel 2: routing, 1024 threads: 4 row-groups x 256 col-pairs
__global__ __launch_bounds__(1024) void routing_kernel(
    const float* __restrict__ x, const float* __restrict__ Wg, const float* __restrict__ bg)
{
    __shared__ float spart[4][Dn];      // per-row-group partial sums
    __shared__ float sscore[En];
    const int b   = blockIdx.x;
    const int tid = threadIdx.x;
    const int grp = tid >> 8;           // 0..3: row group
    const int col = tid & 255;          // column pair index (2 floats)

    const float2* xb = (const float2*)(x + (size_t)b * Sn * Dn);

    // rows [grp*64, grp*64+64): 2 independent accumulator pairs (even/odd rows)
    float e0 = 0.f, e1 = 0.f, o0 = 0.f, o1 = 0.f;
    const float2* p = xb + (size_t)(grp * 64) * 256 + col;
    #pragma unroll 8
    for (int s = 0; s < 64; s += 2) {
        float2 fe = p[(size_t)s * 256];
        float2 fo = p[(size_t)(s + 1) * 256];
        e0 += fe.x; e1 += fe.y;
        o0 += fo.x; o1 += fo.y;
    }
    spart[grp][2 * col]     = e0 + o0;
    spart[grp][2 * col + 1] = e1 + o1;
    __syncthreads();

    // combine 4 partials -> mean (threads 0..511, one column each)
    __shared__ float smean[Dn];
    if (tid < Dn) {
        smean[tid] = (spart[0][tid] + spart[1][tid] + spart[2][tid] + spart[3][tid])
                     * (1.0f / Sn);
    }
    __syncthreads();

    // warps 0..7: fp64 dots, 2 experts each
    const int wid = tid >> 5, lane = tid & 31;
    if (wid < 8) {
        for (int e = wid; e < En; e += 8) {
            double pth = 0.0;
            for (int d = lane; d < Dn; d += 32)
                pth += (double)smean[d] * (double)Wg[d * En + e];
            #pragma unroll
            for (int o = 16; o > 0; o >>= 1)
                pth += __shfl_down_sync(0xFFFFFFFFu, pth, o);
            if (lane == 0) sscore[e] = (float)(pth + (double)bg[e]);
        }
    }
    __syncthreads();

    if (tid == 0) {
        float m = sscore[0];
        int bi = 0;
        #pragma unroll
        for (int e = 1; e < En; e++)
            if (sscore[e] > m) { m = sscore[e]; bi = e; }   // first-max == jnp.argmax
        float den = 0.0f;
        #pragma unroll
        for (int e = 0; e < En; e++) den += expf(sscore[e] - m);
        g_idx[b]  = bi;
        g_gate[b] = 1.0f / den;   // top-1 softmax prob
    }
}

// ---------------- kernel 3: per-batch GEMM, mma.sync tf32 ----------------
// CTA tile M=128 x N=128, K in 16 chunks of 32. 8 warps: 4(M) x 2(N), warp tile 32x64.
// 3 stages x 32KB = 96KB smem -> 2 CTAs/SM. A read raw from x, RNA->tf32 in registers.
#define STAGES 3
#define KC 32
#define A_ST (128 * KC * 4)                 // 16 KB
#define B_ST (128 * KC * 4)                 // 16 KB
#define STAGE_BYTES (A_ST + B_ST)           // 32 KB
#define GEMM_SMEM (STAGES * STAGE_BYTES)    // 96 KB
#define NCHUNK (Dn / KC)                    // 16

__global__ __launch_bounds__(256, 2) void moe_gemm_kernel(
    const float* __restrict__ x, const float* __restrict__ be, float* __restrict__ out)
{
    extern __shared__ char smem[];
    const uint32_t sb = smem_u32(smem);
    const int tid  = threadIdx.x;
    const int wid  = tid >> 5;
    const int lane = tid & 31;

    const int bx = blockIdx.x;
    const int b  = bx >> 3;          // batch
    const int mt = (bx >> 2) & 1;    // M tile (2 x 128)
    const int nt = bx & 3;           // N tile (4 x 128)

    const int   e    = g_idx[b];
    const float gate = g_gate[b];

    const char* agbase = (const char*)(x    + ((size_t)b * Sn + mt * 128) * Dn);
    const char* bgbase = (const char*)(g_wt + ((size_t)e * On + nt * 128) * Dn);

    const int warp_m = wid & 3;      // 0..3 -> 32-row slabs
    const int warp_n = wid >> 2;     // 0..1 -> 64-col slabs

    auto load_stage = [&](int c) {
        const int st = c % STAGES;
        const uint32_t abase = sb + st * STAGE_BYTES;
        const uint32_t bbase = abase + A_ST;
        #pragma unroll
        for (int j = 0; j < 4; j++) {               // A: 1024 x 16B over 256 thr
            int idx = j * 256 + tid;
            int row = idx >> 3, seg = idx & 7;
            uint32_t off = row * 128 + seg * 16;
            cp_async16(abase + SWZ(off), agbase + (size_t)row * (Dn * 4) + c * (KC * 4) + seg * 16);
        }
        #pragma unroll
        for (int j = 0; j < 4; j++) {               // B: 1024 x 16B
            int idx = j * 256 + tid;
            int row = idx >> 3, seg = idx & 7;
            uint32_t off = row * 128 + seg * 16;
            cp_async16(bbase + SWZ(off), bgbase + (size_t)row * (Dn * 4) + c * (KC * 4) + seg * 16);
        }
        CP_COMMIT();
    };

    float acc[2][8][4];
    #pragma unroll
    for (int i = 0; i < 2; i++)
        #pragma unroll
        for (int j = 0; j < 8; j++)
            #pragma unroll
            for (int k = 0; k < 4; k++) acc[i][j][k] = 0.f;

    load_stage(0);
    load_stage(1);

    // ldmatrix lane->address precomputation
    const int a_row  = warp_m * 32 + (lane & 15);
    const int a_kh   = (lane >> 4);
    const int b_row0 = warp_n * 64 + ((lane >> 4) << 3) + (lane & 7);
    const int b_kh   = (lane >> 3) & 1;

    for (int c = 0; c < NCHUNK; c++) {
        if (c < NCHUNK - 1) { CP_WAIT(1); } else { CP_WAIT(0); }
        __syncthreads();
        // Single barrier per chunk: all warps finished compute(c-1) before any
        // passes this barrier, so overwriting stage (c+2)%3 == (c-1)%3 is safe.
        if (c + 2 < NCHUNK) load_stage(c + 2);

        const uint32_t abase = sb + (c % STAGES) * STAGE_BYTES;
        const uint32_t bbase = abase + A_ST;

        #pragma unroll
        for (int ks = 0; ks < 4; ks++) {
            // B LDSMs first: their latency overlaps the A cvt chain below
            uint32_t bf[8][2];
            #pragma unroll
            for (int np = 0; np < 4; np++) {
                uint32_t off = (b_row0 + np * 16) * 128 + ks * 32 + b_kh * 16;
                LDSM_X4(bf[np * 2][0], bf[np * 2][1], bf[np * 2 + 1][0], bf[np * 2 + 1][1],
                        bbase + SWZ(off));
            }

            uint32_t a[2][4];
            #pragma unroll
            for (int mf = 0; mf < 2; mf++) {
                uint32_t off = (a_row + mf * 16) * 128 + ks * 32 + a_kh * 16;
                LDSM_X4(a[mf][0], a[mf][1], a[mf][2], a[mf][3], abase + SWZ(off));
            }
            // RNA-round A to tf32 in registers (raw fp32 would truncate -> bias)
            #pragma unroll
            for (int mf = 0; mf < 2; mf++)
                #pragma unroll
                for (int i = 0; i < 4; i++) cvt_tf32_inplace(a[mf][i]);

            #pragma unroll
            for (int mf = 0; mf < 2; mf++)
                #pragma unroll
                for (int nf = 0; nf < 8; nf++)
                    MMA_TF32(acc[mf][nf], a[mf], bf[nf]);
        }
    }

    // epilogue: gate * (acc + bias)
    const int g = lane >> 2, t = lane & 3;
    const float* bias = be + (size_t)e * On + nt * 128 + warp_n * 64;
    float* obase = out + ((size_t)b * Sn + mt * 128 + warp_m * 32 + g) * On
                       + nt * 128 + warp_n * 64;
    #pragma unroll
    for (int mf = 0; mf < 2; mf++) {
        #pragma unroll
        for (int nf = 0; nf < 8; nf++) {
            int col = nf * 8 + t * 2;
            float b0 = __ldg(bias + col);
            float b1 = __ldg(bias + col + 1);
            float2 v0, v1;
            v0.x = gate * (acc[mf][nf][0] + b0);
            v0.y = gate * (acc[mf][nf][1] + b1);
            v1.x = gate * (acc[mf][nf][2] + b0);
            v1.y = gate * (acc[mf][nf][3] + b1);
            *(float2*)(obase + (size_t)(mf * 16) * On + col)     = v0;
            *(float2*)(obase + (size_t)(mf * 16 + 8) * On + col) = v1;
        }
    }
}

// ---------------- entry point ----------------
extern "C" void kernel_launch(void* const* d_in, const int* in_sizes, int n_in,
                              void* d_out, int out_size)
{
    const float* x  = (const float*)d_in[0];
    const float* Wg = (const float*)d_in[1];
    const float* bg = (const float*)d_in[2];
    const float* We = (const float*)d_in[3];
    const float* be = (const float*)d_in[4];
    float* out = (float*)d_out;

    cudaFuncSetAttribute(moe_gemm_kernel,
                         cudaFuncAttributeMaxDynamicSharedMemorySize, GEMM_SMEM);

    routing_kernel<<<Bn, 1024>>>(x, Wg, bg);
    prep_w_kernel<<<dim3(Dn / 32, On / 32, En), dim3(32, 8)>>>(We);
    moe_gemm_kernel<<<Bn * 8, 256, GEMM_SMEM>>>(x, be, out);
}